// round 15
// baseline (speedup 1.0000x reference)
#include <cuda_runtime.h>
#include <cstdint>
#include <math.h>

#define NN   50000
#define NE   800000
#define NF   100
#define TDIM 100
#define TBL  8192
#define EPB  64         // edges per tile
#define NPB  64         // nodes per block (staged)
#define NODE_BLOCKS ((NN + NPB - 1) / NPB)     // 782
#define TBL_BLOCKS  ((TBL + 1 + 255) / 256)    // 33

// ---------------- scratch (static __device__, no allocation) ----------------
__device__ float4 g_wl0[25], g_wl1[25], g_wr0[25], g_wr1[25];   // node attn-folded weights
__device__ float4 g_we0[25], g_we1[25];                         // edge raw-feature folded weights
__device__ float  g_weT0[TDIM], g_weT1[TDIM];                   // temporal folded weights
__device__ float  g_bl[2], g_br[2], g_be[2];
__device__ float4 g_tbl[TBL + 1];                               // {g0, g1, dg0, dg1} (b_e baked in)
__device__ float4 g_elts[NN];                                   // {el0, el1, node_ts, 0}
__device__ float2 g_er[NN];
__device__ float4 g_acc[NN];                                    // {den0, num0, den1, num1}
__device__ float  g_add[NN];                                    // final per-node residual scalar

__device__ __forceinline__ void mbar_init(unsigned long long* mbar) {
    unsigned m = (unsigned)__cvta_generic_to_shared(mbar);
    asm volatile("mbarrier.init.shared.b64 [%0], 1;" :: "r"(m) : "memory");
}
__device__ __forceinline__ void bulk_ld(void* dst_smem, const void* src,
                                        unsigned bytes, unsigned long long* mbar) {
    unsigned d = (unsigned)__cvta_generic_to_shared(dst_smem);
    unsigned m = (unsigned)__cvta_generic_to_shared(mbar);
    asm volatile("mbarrier.arrive.expect_tx.shared.b64 _, [%0], %1;" :: "r"(m), "r"(bytes) : "memory");
    asm volatile("cp.async.bulk.shared::cluster.global.mbarrier::complete_tx::bytes [%0], [%1], %2, [%3];"
                 :: "r"(d), "l"(src), "r"(bytes), "r"(m) : "memory");
}
__device__ __forceinline__ void mbar_wait(unsigned long long* mbar) {
    unsigned m = (unsigned)__cvta_generic_to_shared(mbar);
    asm volatile(
        "{\n\t"
        ".reg .pred P;\n\t"
        "W%=:\n\t"
        "mbarrier.try_wait.parity.acquire.cta.shared::cta.b64 P, [%0], 0, 0x989680;\n\t"
        "@P bra D%=;\n\t"
        "bra W%=;\n\t"
        "D%=:\n\t"
        "}" :: "r"(m) : "memory");
}

// ---------------- pass 0: fold attention vectors into fc weights ------------
__global__ void prep_kernel(const float* __restrict__ fc_node_w,
                            const float* __restrict__ fc_node_b,
                            const float* __restrict__ fc_edge_w,
                            const float* __restrict__ fc_edge_b,
                            const float* __restrict__ attn_l,
                            const float* __restrict__ attn_r,
                            const float* __restrict__ attn_e) {
    int t = blockIdx.x * blockDim.x + threadIdx.x;
    if (t >= 806) return;
    if (t < 800) {
        int base = (t < 200) ? 0 : (t < 400 ? 200 : 400);
        int u = t - base;
        int k = u >> 1, h = u & 1;
        const float4* wr;
        const float4* a;
        if (t < 200)      { wr = (const float4*)(fc_node_w + k * 200 + h * 100); a = (const float4*)(attn_l + h * 100); }
        else if (t < 400) { wr = (const float4*)(fc_node_w + k * 200 + h * 100); a = (const float4*)(attn_r + h * 100); }
        else              { wr = (const float4*)(fc_edge_w + k * 200 + h * 100); a = (const float4*)(attn_e + h * 100); }
        float s = 0.f;
        #pragma unroll
        for (int f = 0; f < 25; f++) {
            float4 wv = wr[f], av = a[f];
            s += wv.x*av.x + wv.y*av.y + wv.z*av.z + wv.w*av.w;
        }
        if (t < 200)      ((float*)(h ? g_wl1 : g_wl0))[k] = s;
        else if (t < 400) ((float*)(h ? g_wr1 : g_wr0))[k] = s;
        else if (k < 100) ((float*)(h ? g_we1 : g_we0))[k] = s;
        else              (h ? g_weT1 : g_weT0)[k - 100] = s;
    } else {
        int u = t - 800, h = u & 1;
        float s = 0.f;
        if (u < 2)      { for (int f = 0; f < 100; f++) s += fc_node_b[h*100+f] * attn_l[h*100+f]; g_bl[h] = s; }
        else if (u < 4) { for (int f = 0; f < 100; f++) s += fc_node_b[h*100+f] * attn_r[h*100+f]; g_br[h] = s; }
        else            { for (int f = 0; f < 100; f++) s += fc_edge_b[h*100+f] * attn_e[h*100+f]; g_be[h] = s; }
    }
}

// ---------------- pass 1: node el/er + acc zero, and temporal table ---------
__global__ void __launch_bounds__(256) node_table_kernel(const float* __restrict__ memory,
                                                         const float* __restrict__ node_ts,
                                                         const float* __restrict__ time_w,
                                                         const float* __restrict__ time_b) {
    __shared__ __align__(128) float4 tile[NPB * 25];   // 25.6 KB
    __shared__ float4 swl0[25], swl1[25], swr0[25], swr1[25];
    __shared__ unsigned long long mbar;
    int tid = threadIdx.x;

    if (blockIdx.x >= NODE_BLOCKS) {                   // ---- table part ----
        int i = (blockIdx.x - NODE_BLOCKS) * 256 + tid;
        if (i > TBL) return;
        const float dx = 2.0f / (float)TBL;
        float x  = -1.0f + i * dx;
        float x2 = x + dx;
        float v0 = 0.f, v1 = 0.f, u0 = 0.f, u1 = 0.f;
        for (int j = 0; j < TDIM; j++) {
            float w = time_w[j], b = time_b[j];
            float c  = __cosf(fmaf(x,  w, b));
            float c2 = __cosf(fmaf(x2, w, b));
            float e0 = g_weT0[j], e1 = g_weT1[j];
            v0 += c  * e0; v1 += c  * e1;
            u0 += c2 * e0; u1 += c2 * e1;
        }
        float b0 = g_be[0], b1 = g_be[1];
        g_tbl[i] = make_float4(v0 + b0, v1 + b1, u0 - v0, u1 - v1);
        return;
    }

    // ---- node part ----
    int n0  = blockIdx.x * NPB;
    int rem = NN - n0; if (rem > NPB) rem = NPB;
    int lim = rem * 25;

    if (tid == 0) mbar_init(&mbar);
    __syncthreads();
    if (tid == 0)
        bulk_ld(tile, (const float4*)memory + (size_t)n0 * 25, lim * 16, &mbar);

    if (tid < 25)       swl0[tid]      = g_wl0[tid];
    else if (tid < 50)  swl1[tid - 25] = g_wl1[tid - 25];
    else if (tid < 75)  swr0[tid - 50] = g_wr0[tid - 50];
    else if (tid < 100) swr1[tid - 75] = g_wr1[tid - 75];

    mbar_wait(&mbar);
    __syncthreads();

    int e = tid >> 2;                 // local node
    int q = tid & 3;
    int j0  = q * 6 + (q ? 1 : 0);    // 0,7,13,19
    int cnt = q ? 6 : 7;
    float l0 = 0.f, l1 = 0.f, r0 = 0.f, r1 = 0.f;
    const float4* row = tile + e * 25;
    for (int i = 0; i < cnt; i++) {
        float4 m = row[j0 + i];
        float4 w = swl0[j0 + i]; l0 += m.x*w.x + m.y*w.y + m.z*w.z + m.w*w.w;
        w = swl1[j0 + i];        l1 += m.x*w.x + m.y*w.y + m.z*w.z + m.w*w.w;
        w = swr0[j0 + i];        r0 += m.x*w.x + m.y*w.y + m.z*w.z + m.w*w.w;
        w = swr1[j0 + i];        r1 += m.x*w.x + m.y*w.y + m.z*w.z + m.w*w.w;
    }
    #pragma unroll
    for (int o = 1; o <= 2; o <<= 1) {
        l0 += __shfl_xor_sync(0xffffffffu, l0, o);
        l1 += __shfl_xor_sync(0xffffffffu, l1, o);
        r0 += __shfl_xor_sync(0xffffffffu, r0, o);
        r1 += __shfl_xor_sync(0xffffffffu, r1, o);
    }
    if (q == 0 && e < rem) {
        int n = n0 + e;
        float ts = node_ts[n];
        g_elts[n] = make_float4(l0 + g_bl[0], l1 + g_bl[1], ts, 0.f);
        g_er[n]   = make_float2(r0 + g_br[0], r1 + g_br[1]);
        g_acc[n]  = make_float4(0.f, 0.f, 0.f, 0.f);
    }
}

// ---------------- pass 2: edge sweep (2 pipelined tiles per block) ----------
__global__ void __launch_bounds__(256) edge_kernel(const float* __restrict__ raw,
                                                   const float* __restrict__ edge_ts,
                                                   const int*   __restrict__ src,
                                                   const int*   __restrict__ dst) {
    extern __shared__ __align__(128) float4 dyn[];     // 2 tiles * 1600 float4 = 51.2 KB
    __shared__ float4 sw0[25], sw1[25];
    __shared__ __align__(8) unsigned long long mbar[2];
    int tid = threadIdx.x;
    int e0  = blockIdx.x * (2 * EPB);

    if (tid == 0) { mbar_init(&mbar[0]); mbar_init(&mbar[1]); }
    __syncthreads();
    if (tid == 0) {
        const float4* g = (const float4*)raw + (size_t)e0 * 25;
        bulk_ld(dyn,              g,            EPB * 25 * 16, &mbar[0]);
        bulk_ld(dyn + EPB * 25,   g + EPB * 25, EPB * 25 * 16, &mbar[1]);
    }

    if (tid < 25)      sw0[tid]      = g_we0[tid];
    else if (tid < 50) sw1[tid - 25] = g_we1[tid - 25];
    __syncthreads();

    int e = tid >> 2;                 // local edge within tile
    int q = tid & 3;
    int j0  = q * 6 + (q ? 1 : 0);    // 0,7,13,19
    int cnt = q ? 6 : 7;

    #pragma unroll
    for (int half = 0; half < 2; half++) {
        mbar_wait(&mbar[half]);

        int eg = e0 + half * EPB + e;
        int s = 0, d = 0;
        float ets = 0.f;
        if (q == 0) { s = src[eg]; d = dst[eg]; ets = edge_ts[eg]; }

        float a0 = 0.f, a1 = 0.f;
        const float4* row = dyn + half * (EPB * 25) + e * 25;
        for (int i = 0; i < cnt; i++) {
            float4 r = row[j0 + i];
            float4 w = sw0[j0 + i]; a0 += r.x*w.x + r.y*w.y + r.z*w.z + r.w*w.w;
            w = sw1[j0 + i];        a1 += r.x*w.x + r.y*w.y + r.z*w.z + r.w*w.w;
        }
        a0 += __shfl_xor_sync(0xffffffffu, a0, 1);
        a1 += __shfl_xor_sync(0xffffffffu, a1, 1);
        a0 += __shfl_xor_sync(0xffffffffu, a0, 2);
        a1 += __shfl_xor_sync(0xffffffffu, a1, 2);

        if (q == 0) {                 // scatter tail (8 lanes/warp)
            float4 el4 = g_elts[s];                       // {el0, el1, ts_s, 0}
            float2 er2 = g_er[d];
            float u = (ets - el4.z + 1.0f) * ((float)TBL * 0.5f);
            u = fminf(fmaxf(u, 0.0f), (float)TBL - 0.001f);
            int   i  = (int)u;
            float fr = u - (float)i;
            float4 tb = g_tbl[i];
            float elp0 = el4.x + a0 + fmaf(tb.z, fr, tb.x); // el_prime head 0 (b_e in table)
            float elp1 = el4.y + a1 + fmaf(tb.w, fr, tb.y); // el_prime head 1
            float ev0 = elp0 + er2.x;
            float ev1 = elp1 + er2.y;
            ev0 = ev0 > 0.f ? ev0 : 0.2f * ev0;             // leaky relu
            ev1 = ev1 > 0.f ? ev1 : 0.2f * ev1;
            float p0 = __expf(ev0);
            float p1 = __expf(ev1);
            float n0v = p0 * elp0;
            float n1v = p1 * elp1;
            asm volatile("red.global.add.v4.f32 [%0], {%1, %2, %3, %4};"
                         :: "l"(&g_acc[d]), "f"(p0), "f"(n0v), "f"(p1), "f"(n1v)
                         : "memory");
        }
    }
}

// ---------------- pass 3a: per-node residual scalar -------------------------
__global__ void add_kernel() {
    int n = blockIdx.x * blockDim.x + threadIdx.x;
    if (n >= NN) return;
    float4 acc = g_acc[n];
    float ft = (acc.x > 0.f ? __fdividef(acc.y, acc.x) : 0.f)
             + (acc.z > 0.f ? __fdividef(acc.w, acc.z) : 0.f);
    g_add[n] = 0.5f * ft;
}

// ---------------- pass 3b: output (pure stream + hot scalar) ----------------
__global__ void out_kernel(const float4* __restrict__ mem4, float4* __restrict__ out4) {
    int idx = blockIdx.x * blockDim.x + threadIdx.x;
    if (idx >= NN * 25) return;
    float add = g_add[idx / 25];
    float4 m = mem4[idx];
    out4[idx] = make_float4(m.x + add, m.y + add, m.z + add, m.w + add);
}

// ---------------- launch -----------------------------------------------------
extern "C" void kernel_launch(void* const* d_in, const int* in_sizes, int n_in,
                              void* d_out, int out_size) {
    const float* memory    = (const float*)d_in[0];
    const float* node_ts   = (const float*)d_in[1];
    const float* raw       = (const float*)d_in[2];
    const float* edge_ts   = (const float*)d_in[3];
    const float* time_w    = (const float*)d_in[4];
    const float* time_b    = (const float*)d_in[5];
    const float* fc_node_w = (const float*)d_in[6];
    const float* fc_node_b = (const float*)d_in[7];
    const float* fc_edge_w = (const float*)d_in[8];
    const float* fc_edge_b = (const float*)d_in[9];
    const float* attn_l    = (const float*)d_in[10];
    const float* attn_r    = (const float*)d_in[11];
    const float* attn_e    = (const float*)d_in[12];
    const int*   src       = (const int*)d_in[13];
    const int*   dst       = (const int*)d_in[14];
    float* out = (float*)d_out;

    const int EDGE_SMEM = 2 * EPB * 25 * 16;   // 51200 bytes
    cudaFuncSetAttribute(edge_kernel, cudaFuncAttributeMaxDynamicSharedMemorySize, EDGE_SMEM);

    prep_kernel<<<7, 128>>>(fc_node_w, fc_node_b, fc_edge_w, fc_edge_b,
                            attn_l, attn_r, attn_e);
    node_table_kernel<<<NODE_BLOCKS + TBL_BLOCKS, 256>>>(memory, node_ts, time_w, time_b);
    edge_kernel<<<NE / (2 * EPB), 256, EDGE_SMEM>>>(raw, edge_ts, src, dst);
    add_kernel<<<(NN + 255) / 256, 256>>>();
    out_kernel<<<(NN * 25 + 255) / 256, 256>>>((const float4*)memory, (float4*)out);
}

// round 16
// speedup vs baseline: 1.0422x; 1.0422x over previous
#include <cuda_runtime.h>
#include <cstdint>
#include <math.h>

#define NN   50000
#define NE   800000
#define NF   100
#define TDIM 100
#define TBL  8192
#define EPB  64
#define NPB  64
#define PREP_BLOCKS 4
#define NODE_BLOCKS ((NN + NPB - 1) / NPB)               // 782
#define TBL_BLOCKS  ((TBL + 1 + 255) / 256)              // 33
#define SETUP_BLOCKS (PREP_BLOCKS + NODE_BLOCKS + TBL_BLOCKS)  // 819
#define NODE_TARGET (NODE_BLOCKS + TBL_BLOCKS)           // 815
#define EDGE_BLOCKS (NE / EPB)                           // 12500

// ---------------- scratch (static __device__, no allocation) ----------------
__device__ float4 g_wl0[25], g_wl1[25], g_wr0[25], g_wr1[25];
__device__ float4 g_we0[25], g_we1[25];
__device__ float  g_weT0[TDIM], g_weT1[TDIM];
__device__ float  g_bl[2], g_br[2], g_be[2];
__device__ float4 g_tbl[TBL + 1];
__device__ float4 g_elts[NN];                            // {el0, el1, node_ts, 0}
__device__ float2 g_er[NN];
__device__ float4 g_acc[NN];                             // {den0, num0, den1, num1}
__device__ unsigned g_done_prep = 0;
__device__ unsigned g_done_node = 0;

__device__ __forceinline__ void mbar_init(unsigned long long* mbar) {
    unsigned m = (unsigned)__cvta_generic_to_shared(mbar);
    asm volatile("mbarrier.init.shared.b64 [%0], 1;" :: "r"(m) : "memory");
}
__device__ __forceinline__ void bulk_ld(void* dst_smem, const void* src,
                                        unsigned bytes, unsigned long long* mbar) {
    unsigned d = (unsigned)__cvta_generic_to_shared(dst_smem);
    unsigned m = (unsigned)__cvta_generic_to_shared(mbar);
    asm volatile("mbarrier.arrive.expect_tx.shared.b64 _, [%0], %1;" :: "r"(m), "r"(bytes) : "memory");
    asm volatile("cp.async.bulk.shared::cluster.global.mbarrier::complete_tx::bytes [%0], [%1], %2, [%3];"
                 :: "r"(d), "l"(src), "r"(bytes), "r"(m) : "memory");
}
__device__ __forceinline__ void mbar_wait(unsigned long long* mbar) {
    unsigned m = (unsigned)__cvta_generic_to_shared(mbar);
    asm volatile(
        "{\n\t"
        ".reg .pred P;\n\t"
        "W%=:\n\t"
        "mbarrier.try_wait.parity.acquire.cta.shared::cta.b64 P, [%0], 0, 0x989680;\n\t"
        "@P bra D%=;\n\t"
        "bra W%=;\n\t"
        "D%=:\n\t"
        "}" :: "r"(m) : "memory");
}
__device__ __forceinline__ void spin_until(unsigned* p, unsigned tgt) {
    unsigned v;
    while (true) {
        asm volatile("ld.acquire.gpu.u32 %0, [%1];" : "=r"(v) : "l"(p) : "memory");
        if (v >= tgt) break;
        __nanosleep(64);
    }
}

// ================= mega kernel: prep | node | table | edge ===================
__global__ void __launch_bounds__(256) mega_kernel(
    const float* __restrict__ memory,   const float* __restrict__ node_ts,
    const float* __restrict__ time_w,   const float* __restrict__ time_b,
    const float* __restrict__ raw,      const float* __restrict__ edge_ts,
    const int*   __restrict__ src,      const int*   __restrict__ dst,
    const float* __restrict__ fc_node_w, const float* __restrict__ fc_node_b,
    const float* __restrict__ fc_edge_w, const float* __restrict__ fc_edge_b,
    const float* __restrict__ attn_l,   const float* __restrict__ attn_r,
    const float* __restrict__ attn_e)
{
    __shared__ __align__(128) float4 tile[EPB * 25];     // 25.6 KB (reused by node/edge)
    __shared__ float4 sw[4][25];
    __shared__ unsigned long long mbar;
    int tid = threadIdx.x;
    int bid = blockIdx.x;

    // ---------------- PREP path (bids 0..3) ----------------
    if (bid < PREP_BLOCKS) {
        int t = bid * 256 + tid;
        if (t < 800) {
            int base = (t < 200) ? 0 : (t < 400 ? 200 : 400);
            int u = t - base;
            int k = u >> 1, h = u & 1;
            const float4* wr;
            const float4* a;
            if (t < 200)      { wr = (const float4*)(fc_node_w + k * 200 + h * 100); a = (const float4*)(attn_l + h * 100); }
            else if (t < 400) { wr = (const float4*)(fc_node_w + k * 200 + h * 100); a = (const float4*)(attn_r + h * 100); }
            else              { wr = (const float4*)(fc_edge_w + k * 200 + h * 100); a = (const float4*)(attn_e + h * 100); }
            float s = 0.f;
            #pragma unroll
            for (int f = 0; f < 25; f++) {
                float4 wv = wr[f], av = a[f];
                s += wv.x*av.x + wv.y*av.y + wv.z*av.z + wv.w*av.w;
            }
            if (t < 200)      ((float*)(h ? g_wl1 : g_wl0))[k] = s;
            else if (t < 400) ((float*)(h ? g_wr1 : g_wr0))[k] = s;
            else if (k < 100) ((float*)(h ? g_we1 : g_we0))[k] = s;
            else              (h ? g_weT1 : g_weT0)[k - 100] = s;
        } else if (t < 806) {
            int u = t - 800, h = u & 1;
            float s = 0.f;
            if (u < 2)      { for (int f = 0; f < 100; f++) s += fc_node_b[h*100+f] * attn_l[h*100+f]; g_bl[h] = s; }
            else if (u < 4) { for (int f = 0; f < 100; f++) s += fc_node_b[h*100+f] * attn_r[h*100+f]; g_br[h] = s; }
            else            { for (int f = 0; f < 100; f++) s += fc_edge_b[h*100+f] * attn_e[h*100+f]; g_be[h] = s; }
        }
        __threadfence();
        __syncthreads();
        if (tid == 0) atomicAdd(&g_done_prep, 1u);
        return;
    }

    // ---------------- NODE path ----------------
    if (bid < PREP_BLOCKS + NODE_BLOCKS) {
        int n0  = (bid - PREP_BLOCKS) * NPB;
        int rem = NN - n0; if (rem > NPB) rem = NPB;
        int lim = rem * 25;

        if (tid == 0) mbar_init(&mbar);
        __syncthreads();
        if (tid == 0) {
            bulk_ld(tile, (const float4*)memory + (size_t)n0 * 25, lim * 16, &mbar);
            spin_until(&g_done_prep, PREP_BLOCKS);
        }
        __syncthreads();                                  // prep results visible

        if (tid < 25)       sw[0][tid]      = g_wl0[tid];
        else if (tid < 50)  sw[1][tid - 25] = g_wl1[tid - 25];
        else if (tid < 75)  sw[2][tid - 50] = g_wr0[tid - 50];
        else if (tid < 100) sw[3][tid - 75] = g_wr1[tid - 75];

        mbar_wait(&mbar);
        __syncthreads();

        int e = tid >> 2;
        int q = tid & 3;
        int j0  = q * 6 + (q ? 1 : 0);
        int cnt = q ? 6 : 7;
        float l0 = 0.f, l1 = 0.f, r0 = 0.f, r1 = 0.f;
        const float4* row = tile + e * 25;
        for (int i = 0; i < cnt; i++) {
            float4 m = row[j0 + i];
            float4 w = sw[0][j0 + i]; l0 += m.x*w.x + m.y*w.y + m.z*w.z + m.w*w.w;
            w = sw[1][j0 + i];        l1 += m.x*w.x + m.y*w.y + m.z*w.z + m.w*w.w;
            w = sw[2][j0 + i];        r0 += m.x*w.x + m.y*w.y + m.z*w.z + m.w*w.w;
            w = sw[3][j0 + i];        r1 += m.x*w.x + m.y*w.y + m.z*w.z + m.w*w.w;
        }
        #pragma unroll
        for (int o = 1; o <= 2; o <<= 1) {
            l0 += __shfl_xor_sync(0xffffffffu, l0, o);
            l1 += __shfl_xor_sync(0xffffffffu, l1, o);
            r0 += __shfl_xor_sync(0xffffffffu, r0, o);
            r1 += __shfl_xor_sync(0xffffffffu, r1, o);
        }
        if (q == 0 && e < rem) {
            int n = n0 + e;
            float ts = node_ts[n];
            g_elts[n] = make_float4(l0 + g_bl[0], l1 + g_bl[1], ts, 0.f);
            g_er[n]   = make_float2(r0 + g_br[0], r1 + g_br[1]);
            g_acc[n]  = make_float4(0.f, 0.f, 0.f, 0.f);
        }
        __threadfence();
        __syncthreads();
        if (tid == 0) atomicAdd(&g_done_node, 1u);
        return;
    }

    // ---------------- TABLE path ----------------
    if (bid < SETUP_BLOCKS) {
        if (tid == 0) spin_until(&g_done_prep, PREP_BLOCKS);
        __syncthreads();
        int i = (bid - PREP_BLOCKS - NODE_BLOCKS) * 256 + tid;
        if (i <= TBL) {
            const float dx = 2.0f / (float)TBL;
            float x  = -1.0f + i * dx;
            float x2 = x + dx;
            float v0 = 0.f, v1 = 0.f, u0 = 0.f, u1 = 0.f;
            for (int j = 0; j < TDIM; j++) {
                float w = time_w[j], b = time_b[j];
                float c  = __cosf(fmaf(x,  w, b));
                float c2 = __cosf(fmaf(x2, w, b));
                float e0 = g_weT0[j], e1 = g_weT1[j];
                v0 += c  * e0; v1 += c  * e1;
                u0 += c2 * e0; u1 += c2 * e1;
            }
            float b0 = g_be[0], b1 = g_be[1];
            g_tbl[i] = make_float4(v0 + b0, v1 + b1, u0 - v0, u1 - v1);
        }
        __threadfence();
        __syncthreads();
        if (tid == 0) atomicAdd(&g_done_node, 1u);
        return;
    }

    // ---------------- EDGE path ----------------
    int e0 = (bid - SETUP_BLOCKS) * EPB;

    if (tid == 0) mbar_init(&mbar);
    __syncthreads();
    if (tid == 0) {
        bulk_ld(tile, (const float4*)raw + (size_t)e0 * 25, EPB * 25 * 16, &mbar);
        spin_until(&g_done_prep, PREP_BLOCKS);
    }
    __syncthreads();                                      // prep (g_we) visible

    if (tid < 25)      sw[0][tid]      = g_we0[tid];
    else if (tid < 50) sw[1][tid - 25] = g_we1[tid - 25];

    mbar_wait(&mbar);
    __syncthreads();

    int e = tid >> 2;
    int q = tid & 3;

    int s = 0, d = 0;
    float ets = 0.f;
    if (q == 0) {
        int eg = e0 + e;
        s = src[eg]; d = dst[eg]; ets = edge_ts[eg];
    }

    int j0  = q * 6 + (q ? 1 : 0);
    int cnt = q ? 6 : 7;
    float a0 = 0.f, a1 = 0.f;
    const float4* row = tile + e * 25;
    for (int i = 0; i < cnt; i++) {
        float4 r = row[j0 + i];
        float4 w = sw[0][j0 + i]; a0 += r.x*w.x + r.y*w.y + r.z*w.z + r.w*w.w;
        w = sw[1][j0 + i];        a1 += r.x*w.x + r.y*w.y + r.z*w.z + r.w*w.w;
    }
    a0 += __shfl_xor_sync(0xffffffffu, a0, 1);
    a1 += __shfl_xor_sync(0xffffffffu, a1, 1);
    a0 += __shfl_xor_sync(0xffffffffu, a0, 2);
    a1 += __shfl_xor_sync(0xffffffffu, a1, 2);

    if (tid == 0) spin_until(&g_done_node, NODE_TARGET);  // node/table results ready
    __syncthreads();

    if (q == 0) {
        float4 el4 = g_elts[s];
        float2 er2 = g_er[d];
        float u = (ets - el4.z + 1.0f) * ((float)TBL * 0.5f);
        u = fminf(fmaxf(u, 0.0f), (float)TBL - 0.001f);
        int   i  = (int)u;
        float fr = u - (float)i;
        float4 tb = g_tbl[i];
        float elp0 = el4.x + a0 + fmaf(tb.z, fr, tb.x);
        float elp1 = el4.y + a1 + fmaf(tb.w, fr, tb.y);
        float ev0 = elp0 + er2.x;
        float ev1 = elp1 + er2.y;
        ev0 = ev0 > 0.f ? ev0 : 0.2f * ev0;
        ev1 = ev1 > 0.f ? ev1 : 0.2f * ev1;
        float p0 = __expf(ev0);
        float p1 = __expf(ev1);
        float n0v = p0 * elp0;
        float n1v = p1 * elp1;
        asm volatile("red.global.add.v4.f32 [%0], {%1, %2, %3, %4};"
                     :: "l"(&g_acc[d]), "f"(p0), "f"(n0v), "f"(p1), "f"(n1v)
                     : "memory");
    }
}

// ---------------- pass 2: output (also resets counters for next replay) -----
__global__ void out_kernel(const float4* __restrict__ mem4, float4* __restrict__ out4) {
    if (blockIdx.x == 0 && threadIdx.x == 0) { g_done_prep = 0; g_done_node = 0; }
    int idx = blockIdx.x * blockDim.x + threadIdx.x;
    if (idx >= NN * 25) return;
    int n = idx / 25;
    float4 acc = g_acc[n];
    float ft = (acc.x > 0.f ? __fdividef(acc.y, acc.x) : 0.f)
             + (acc.z > 0.f ? __fdividef(acc.w, acc.z) : 0.f);
    float add = 0.5f * ft;
    float4 m = mem4[idx];
    out4[idx] = make_float4(m.x + add, m.y + add, m.z + add, m.w + add);
}

// ---------------- launch -----------------------------------------------------
extern "C" void kernel_launch(void* const* d_in, const int* in_sizes, int n_in,
                              void* d_out, int out_size) {
    const float* memory    = (const float*)d_in[0];
    const float* node_ts   = (const float*)d_in[1];
    const float* raw       = (const float*)d_in[2];
    const float* edge_ts   = (const float*)d_in[3];
    const float* time_w    = (const float*)d_in[4];
    const float* time_b    = (const float*)d_in[5];
    const float* fc_node_w = (const float*)d_in[6];
    const float* fc_node_b = (const float*)d_in[7];
    const float* fc_edge_w = (const float*)d_in[8];
    const float* fc_edge_b = (const float*)d_in[9];
    const float* attn_l    = (const float*)d_in[10];
    const float* attn_r    = (const float*)d_in[11];
    const float* attn_e    = (const float*)d_in[12];
    const int*   src       = (const int*)d_in[13];
    const int*   dst       = (const int*)d_in[14];
    float* out = (float*)d_out;

    mega_kernel<<<SETUP_BLOCKS + EDGE_BLOCKS, 256>>>(
        memory, node_ts, time_w, time_b, raw, edge_ts, src, dst,
        fc_node_w, fc_node_b, fc_edge_w, fc_edge_b, attn_l, attn_r, attn_e);
    out_kernel<<<(NN * 25 + 255) / 256, 256>>>((const float4*)memory, (float4*)out);
}